// round 6
// baseline (speedup 1.0000x reference)
#include <cuda_runtime.h>
#include <math.h>
#include <cstdint>

#define HD 2048
#define ID 1408
#define NE 16
#define TK 4
#define NT 1024
#define SID 2816
#define RSCALE 2.5f

// ---------------- scratch ----------------
__device__ int   d_cnt[NE];
__device__ int   d_tok[NE * NT];
__device__ float d_wt [NE * NT];
__device__ float d_hbuf[NE * NT * ID];
__device__ float d_hsh [NT * SID];

// ---------------- helpers ----------------
__device__ __forceinline__ uint32_t f2tf(float f) {
    uint32_t r;
    asm("cvt.rna.tf32.f32 %0, %1;" : "=r"(r) : "f"(f));
    return r;
}
__device__ __forceinline__ void mma8(float* c, const uint32_t* a, const uint32_t* b) {
    asm volatile(
        "mma.sync.aligned.m16n8k8.row.col.f32.tf32.tf32.f32 "
        "{%0,%1,%2,%3}, {%4,%5,%6,%7}, {%8,%9}, {%0,%1,%2,%3};"
        : "+f"(c[0]), "+f"(c[1]), "+f"(c[2]), "+f"(c[3])
        : "r"(a[0]), "r"(a[1]), "r"(a[2]), "r"(a[3]), "r"(b[0]), "r"(b[1]));
}
__device__ __forceinline__ float silu(float g) { return g / (1.f + __expf(-g)); }

// Layout: row stride 24 u32; 16 cols stored as 4 groups of 4:
//   g0={c0,c4,c1,c5} g1={c2,c6,c3,c7} g2={c8,c12,c9,c13} g3={c10,c14,c11,c15}
// physical slot of group g = g ^ ((row>>2)&1)  (store + load both apply it)
#define SROW 24
#define STG_U32 6144      // 256 rows * 24 u32 per stage

// cvt + swizzled store of one full row (16 floats in 4 float4s)
__device__ __forceinline__ void sts_row(uint32_t* d, int s,
                                        float4 r0, float4 r1, float4 r2, float4 r3) {
    uint4 g0 = { f2tf(r0.x), f2tf(r1.x), f2tf(r0.y), f2tf(r1.y) };
    uint4 g1 = { f2tf(r0.z), f2tf(r1.z), f2tf(r0.w), f2tf(r1.w) };
    uint4 g2 = { f2tf(r2.x), f2tf(r3.x), f2tf(r2.y), f2tf(r3.y) };
    uint4 g3 = { f2tf(r2.z), f2tf(r3.z), f2tf(r2.w), f2tf(r3.w) };
    *(uint4*)(d + ((0 ^ s) << 2)) = g0;
    *(uint4*)(d + ((1 ^ s) << 2)) = g1;
    *(uint4*)(d + ((2 ^ s) << 2)) = g2;
    *(uint4*)(d + ((3 ^ s) << 2)) = g3;
}

// ---------------- init / memset ----------------
__global__ void init_kernel() {
    if (threadIdx.x < NE) d_cnt[threadIdx.x] = 0;
}
__global__ void zero_out(float4* out) {
    out[blockIdx.x * 256 + threadIdx.x] = make_float4(0.f, 0.f, 0.f, 0.f);
}

// ---------------- gate ----------------
__global__ void gate_kernel(const float* __restrict__ x,
                            const float* __restrict__ gw,
                            const float* __restrict__ gb) {
    const int t = blockIdx.x;
    __shared__ float s_sc[NE];
    const int wid = threadIdx.x >> 5;
    const int lane = threadIdx.x & 31;
    const float* xr = x + (size_t)t * HD;
    const float* wr = gw + (size_t)wid * HD;
    float acc = 0.f;
    for (int k = lane; k < HD; k += 32) acc += xr[k] * wr[k];
    #pragma unroll
    for (int o = 16; o; o >>= 1) acc += __shfl_xor_sync(0xffffffffu, acc, o);
    if (lane == 0) s_sc[wid] = 1.f / (1.f + expf(-acc)) + gb[wid];
    __syncthreads();
    if (threadIdx.x != 0) return;

    float sc[NE];
    #pragma unroll
    for (int e = 0; e < NE; e++) sc[e] = s_sc[e];
    float gs[4];
    #pragma unroll
    for (int g = 0; g < 4; g++) {
        float m = sc[g * 4];
        #pragma unroll
        for (int j = 1; j < 4; j++) m = fmaxf(m, sc[g * 4 + j]);
        gs[g] = m;
    }
    int g0 = 0;
    for (int g = 1; g < 4; g++) if (gs[g] > gs[g0]) g0 = g;
    int g1 = -1;
    for (int g = 0; g < 4; g++) {
        if (g == g0) continue;
        if (g1 < 0 || gs[g] > gs[g1]) g1 = g;
    }
    float masked[NE];
    #pragma unroll
    for (int e = 0; e < NE; e++) {
        int g = e >> 2;
        masked[e] = (g == g0 || g == g1) ? sc[e] : 0.f;
    }
    int idx[TK]; float w[TK]; bool used[NE];
    #pragma unroll
    for (int e = 0; e < NE; e++) used[e] = false;
    float wsum = 0.f;
    for (int k = 0; k < TK; k++) {
        int best = -1;
        for (int e = 0; e < NE; e++) {
            if (used[e]) continue;
            if (best < 0 || masked[e] > masked[best]) best = e;
        }
        used[best] = true;
        idx[k] = best; w[k] = masked[best]; wsum += masked[best];
    }
    const float inv = 1.f / (wsum + 1e-6f);
    for (int k = 0; k < TK; k++) {
        int e = idx[k];
        int pos = atomicAdd(&d_cnt[e], 1);
        d_tok[e * NT + pos] = t;
        d_wt [e * NT + pos] = w[k] * inv * RSCALE;
    }
}

// ---------------- GEMM1: dual gate/up, z<16 routed, z=16/17 shared halves --
// Tile 128M x 64N dual, Kc=16, 2-stage, 1 sync/chunk.
// Stage u32 layout: A rows 0-127 @0 | G rows @3072 | U rows @4608
#define G1_SMEM (512 + 2 * STG_U32 * 4)
__global__ void __launch_bounds__(256, 2)
gemm1_mma(const float* __restrict__ X,
          const float* __restrict__ Wg_r, const float* __restrict__ Wu_r,
          const float* __restrict__ Wg_s, const float* __restrict__ Wu_s,
          float* __restrict__ Hr, float* __restrict__ Hs) {
    const int e = blockIdx.z;
    const bool SHARED = (e >= NE);
    int M, ldH, n0;
    const float *Wg, *Wu; float* Ho;
    if (SHARED) {
        M = NT; ldH = SID;
        Wg = Wg_s; Wu = Wu_s; Ho = Hs;
        n0 = (blockIdx.x + (e == NE + 1 ? 22 : 0)) * 64;
    } else {
        M = d_cnt[e]; ldH = ID;
        Wg = Wg_r + (size_t)e * ID * HD;
        Wu = Wu_r + (size_t)e * ID * HD;
        Ho = Hr + (size_t)e * NT * ID;
        n0 = blockIdx.x * 64;
    }
    const int m0 = blockIdx.y * 128;
    if (m0 >= M) return;

    extern __shared__ char smem[];
    int* s_tok = (int*)smem;
    uint32_t* ST = (uint32_t*)(smem + 512);
    const int tid = threadIdx.x, lane = tid & 31, wid = tid >> 5;
    const int wr = wid >> 2, wc = wid & 3;
    const int l4 = lane >> 2, lm = lane & 3;
    if (!SHARED && tid < 128) s_tok[tid] = (m0 + tid < M) ? d_tok[e * NT + m0 + tid] : 0;
    __syncthreads();

    // loader: thread -> one smem row. 0-127:A, 128-191:G, 192-255:U
    int lrow, lbase;
    const float* lsrc;
    bool aok = true;
    if (tid < 128) {
        lrow = tid; lbase = 0;
        aok = (m0 + tid) < M;
        const int arow = SHARED ? (aok ? m0 + tid : 0) : (aok ? s_tok[tid] : 0);
        lsrc = X + (size_t)arow * HD;
    } else if (tid < 192) {
        lrow = tid - 128; lbase = 3072;
        lsrc = Wg + (size_t)(n0 + lrow) * HD;
    } else {
        lrow = tid - 192; lbase = 4608;
        lsrc = Wu + (size_t)(n0 + lrow) * HD;
    }
    const float4* LP = (const float4*)lsrc;
    const int s_st = (lrow >> 2) & 1;
    uint32_t* dst0 = ST + lbase + lrow * SROW;

    float4 r0, r1, r2, r3;
    const float4 Z = make_float4(0.f, 0.f, 0.f, 0.f);
    auto ldg = [&](int c) {
        if (aok) { r0 = LP[c*4]; r1 = LP[c*4+1]; r2 = LP[c*4+2]; r3 = LP[c*4+3]; }
        else     { r0 = Z; r1 = Z; r2 = Z; r3 = Z; }
    };
    auto sts = [&](int buf) { sts_row(dst0 + buf * STG_U32, s_st, r0, r1, r2, r3); };

    // consumer constants
    const int sX = (l4 >> 2) & 1;
    const int c0 = (((0 + (lm >> 1)) ^ sX) << 2) | ((lm & 1) << 1);   // ks=0
    const int c1 = (((2 + (lm >> 1)) ^ sX) << 2) | ((lm & 1) << 1);   // ks=1
    const int aoff = (wr * 64 + l4) * SROW;
    const int goff = 3072 + (wc * 16 + l4) * SROW;

    float cg[4][2][4] = {}, cu[4][2][4] = {};
    const int C = HD >> 4;
    ldg(0); sts(0); ldg(1);
    __syncthreads();

    #pragma unroll 1
    for (int c = 0; c < C; c++) {
        if (c + 1 < C) sts((c + 1) & 1);
        if (c + 2 < C) ldg(c + 2);
        const uint32_t* S = ST + (c & 1) * STG_U32;
        #pragma unroll
        for (int ks = 0; ks < 2; ks++) {
            const int ck = ks ? c1 : c0;
            uint32_t a[4][4];
            #pragma unroll
            for (int mi = 0; mi < 4; mi++) {
                const uint32_t* pa = S + aoff + mi * (16 * SROW);
                uint2 p = *(const uint2*)(pa + ck);
                uint2 q = *(const uint2*)(pa + 8 * SROW + ck);
                a[mi][0] = p.x; a[mi][1] = q.x; a[mi][2] = p.y; a[mi][3] = q.y;
            }
            #pragma unroll
            for (int ni = 0; ni < 2; ni++) {
                const uint32_t* pg = S + goff + ni * (8 * SROW) + ck;
                uint2 vg = *(const uint2*)pg;
                uint2 vu = *(const uint2*)(pg + 1536);
                uint32_t bg[2] = { vg.x, vg.y };
                uint32_t bu[2] = { vu.x, vu.y };
                #pragma unroll
                for (int mi = 0; mi < 4; mi++) {
                    mma8(cg[mi][ni], a[mi], bg);
                    mma8(cu[mi][ni], a[mi], bu);
                }
            }
        }
        __syncthreads();
    }
    #pragma unroll
    for (int mi = 0; mi < 4; mi++)
        #pragma unroll
        for (int ni = 0; ni < 2; ni++) {
            const int r = m0 + wr * 64 + mi * 16 + l4;
            const int cc = n0 + wc * 16 + ni * 8 + 2 * lm;
            if (r < M) {
                float2 v = { silu(cg[mi][ni][0]) * cu[mi][ni][0],
                             silu(cg[mi][ni][1]) * cu[mi][ni][1] };
                *(float2*)(Ho + (size_t)r * ldH + cc) = v;
            }
            if (r + 8 < M) {
                float2 v = { silu(cg[mi][ni][2]) * cu[mi][ni][2],
                             silu(cg[mi][ni][3]) * cu[mi][ni][3] };
                *(float2*)(Ho + (size_t)(r + 8) * ldH + cc) = v;
            }
        }
}

// ---------------- GEMM2: down, z<16 routed, z=16 shared --------------------
// Tile 128M x 128N, Kc=16, 2-stage, 1 sync/chunk. Stage: A@0 | B@3072
#define G2_SMEM (1024 + 2 * STG_U32 * 4)
__global__ void __launch_bounds__(256, 2)
gemm2_mma(const float* __restrict__ Hr, const float* __restrict__ Wd_r,
          const float* __restrict__ Hs, const float* __restrict__ Wd_s,
          float* __restrict__ Out) {
    const int e = blockIdx.z;
    const bool SHARED = (e == NE);
    int M, K;
    const float *Hin, *Wd;
    if (SHARED) {
        M = NT; K = SID; Hin = Hs; Wd = Wd_s;
    } else {
        M = d_cnt[e]; K = ID;
        Hin = Hr + (size_t)e * NT * ID;
        Wd  = Wd_r + (size_t)e * HD * ID;
    }
    const int m0 = blockIdx.y * 128;
    if (m0 >= M) return;
    const int n0 = blockIdx.x * 128;

    extern __shared__ char smem[];
    int*   s_tok = (int*)smem;
    float* s_wt  = (float*)(smem + 512);
    uint32_t* ST = (uint32_t*)(smem + 1024);
    const int tid = threadIdx.x, lane = tid & 31, wid = tid >> 5;
    const int wr = wid >> 2, wc = wid & 3;
    const int l4 = lane >> 2, lm = lane & 3;
    if (tid < 128) {
        const bool ok = m0 + tid < M;
        if (SHARED) { s_tok[tid] = ok ? m0 + tid : 0; s_wt[tid] = 1.f; }
        else {
            s_tok[tid] = ok ? d_tok[e * NT + m0 + tid] : 0;
            s_wt [tid] = ok ? d_wt [e * NT + m0 + tid] : 0.f;
        }
    }
    __syncthreads();

    int lrow, lbase;
    const float* lsrc;
    bool aok = true;
    if (tid < 128) {
        lrow = tid; lbase = 0;
        aok = (m0 + tid) < M;
        lsrc = Hin + (size_t)(aok ? m0 + tid : 0) * K;
    } else {
        lrow = tid - 128; lbase = 3072;
        lsrc = Wd + (size_t)(n0 + lrow) * K;
    }
    const float4* LP = (const float4*)lsrc;
    const int s_st = (lrow >> 2) & 1;
    uint32_t* dst0 = ST + lbase + lrow * SROW;

    float4 r0, r1, r2, r3;
    const float4 Z = make_float4(0.f, 0.f, 0.f, 0.f);
    auto ldg = [&](int c) {
        if (aok) { r0 = LP[c*4]; r1 = LP[c*4+1]; r2 = LP[c*4+2]; r3 = LP[c*4+3]; }
        else     { r0 = Z; r1 = Z; r2 = Z; r3 = Z; }
    };
    auto sts = [&](int buf) { sts_row(dst0 + buf * STG_U32, s_st, r0, r1, r2, r3); };

    const int sX = (l4 >> 2) & 1;
    const int c0 = (((0 + (lm >> 1)) ^ sX) << 2) | ((lm & 1) << 1);
    const int c1 = (((2 + (lm >> 1)) ^ sX) << 2) | ((lm & 1) << 1);
    const int aoff = (wr * 64 + l4) * SROW;
    const int boff = 3072 + (wc * 32 + l4) * SROW;

    float acc[4][4][4] = {};
    const int C = K >> 4;
    ldg(0); sts(0); ldg(1);
    __syncthreads();

    #pragma unroll 1
    for (int c = 0; c < C; c++) {
        if (c + 1 < C) sts((c + 1) & 1);
        if (c + 2 < C) ldg(c + 2);
        const uint32_t* S = ST + (c & 1) * STG_U32;
        #pragma unroll
        for (int ks = 0; ks < 2; ks++) {
            const int ck = ks ? c1 : c0;
            uint32_t a[4][4];
            #pragma unroll
            for (int mi = 0; mi < 4; mi++) {
                const uint32_t* pa = S + aoff + mi * (16 * SROW);
                uint2 p = *(const uint2*)(pa + ck);
                uint2 q = *(const uint2*)(pa + 8 * SROW + ck);
                a[mi][0] = p.x; a[mi][1] = q.x; a[mi][2] = p.y; a[mi][3] = q.y;
            }
            #pragma unroll
            for (int ni = 0; ni < 4; ni++) {
                uint2 vb = *(const uint2*)(S + boff + ni * (8 * SROW) + ck);
                uint32_t b[2] = { vb.x, vb.y };
                #pragma unroll
                for (int mi = 0; mi < 4; mi++)
                    mma8(acc[mi][ni], a[mi], b);
            }
        }
        __syncthreads();
    }
    #pragma unroll
    for (int mi = 0; mi < 4; mi++) {
        const int rl0 = wr * 64 + mi * 16 + l4;
        #pragma unroll
        for (int ni = 0; ni < 4; ni++) {
            const int cc = n0 + wc * 32 + ni * 8 + 2 * lm;
            #pragma unroll
            for (int hh = 0; hh < 2; hh++) {
                const int rl = rl0 + hh * 8;
                if (m0 + rl >= M) continue;
                const float w = s_wt[rl];
                float* o = Out + (size_t)s_tok[rl] * HD + cc;
                atomicAdd(o + 0, w * acc[mi][ni][2 * hh + 0]);
                atomicAdd(o + 1, w * acc[mi][ni][2 * hh + 1]);
            }
        }
    }
}

// ---------------- launch ----------------
extern "C" void kernel_launch(void* const* d_in, const int* in_sizes, int n_in,
                              void* d_out, int out_size) {
    const float* x       = (const float*)d_in[0];
    const float* gate_w  = (const float*)d_in[1];
    const float* gate_b  = (const float*)d_in[2];
    const float* w_gate  = (const float*)d_in[3];
    const float* w_up    = (const float*)d_in[4];
    const float* w_down  = (const float*)d_in[5];
    const float* sw_gate = (const float*)d_in[6];
    const float* sw_up   = (const float*)d_in[7];
    const float* sw_down = (const float*)d_in[8];
    float* out = (float*)d_out;

    float* hbuf; cudaGetSymbolAddress((void**)&hbuf, d_hbuf);
    float* hsh;  cudaGetSymbolAddress((void**)&hsh,  d_hsh);

    cudaFuncSetAttribute(gemm1_mma, cudaFuncAttributeMaxDynamicSharedMemorySize, G1_SMEM);
    cudaFuncSetAttribute(gemm2_mma, cudaFuncAttributeMaxDynamicSharedMemorySize, G2_SMEM);

    zero_out<<<(NT * HD) / 1024, 256>>>((float4*)out);
    init_kernel<<<1, 32>>>();
    gate_kernel<<<NT, 512>>>(x, gate_w, gate_b);

    // gemm1: z 0..15 routed (22 n-tiles), z 16..17 = shared halves (22 each)
    gemm1_mma<<<dim3(22, NT / 128, NE + 2), 256, G1_SMEM>>>(
        x, w_gate, w_up, sw_gate, sw_up, hbuf, hsh);
    // gemm2: z 0..15 routed, z 16 shared; atomic accumulate into zeroed out
    gemm2_mma<<<dim3(HD / 128, NT / 128, NE + 1), 256, G2_SMEM>>>(
        hbuf, w_down, hsh, sw_down, out);
}

// round 7
// speedup vs baseline: 1.6534x; 1.6534x over previous
#include <cuda_runtime.h>
#include <math.h>
#include <cstdint>

#define HD 2048
#define ID 1408
#define NE 16
#define TK 4
#define NT 1024
#define SID 2816
#define RSCALE 2.5f

// ---------------- scratch ----------------
__device__ int   d_cnt[NE];
__device__ int   d_tok[NE * NT];
__device__ float d_wt [NE * NT];
__device__ float d_xr  [NT * HD];        // tf32-rounded copy of x
__device__ float d_hbuf[NE * NT * ID];   // per-expert h (tf32-rounded)
__device__ float d_hsh [NT * SID];       // shared-expert h (tf32-rounded)

// ---------------- PTX helpers ----------------
__device__ __forceinline__ uint32_t smem_u32(const void* p) {
    uint32_t a;
    asm("{ .reg .u64 t; cvta.to.shared.u64 t, %1; cvt.u32.u64 %0, t; }"
        : "=r"(a) : "l"(p));
    return a;
}
#define CP_ASYNC(dst, src, sz) \
    asm volatile("cp.async.cg.shared.global [%0], [%1], 16, %2;" \
                 :: "r"(dst), "l"(src), "r"(sz) : "memory")
#define CP_COMMIT() asm volatile("cp.async.commit_group;" ::: "memory")
#define CP_WAIT(n)  asm volatile("cp.async.wait_group %0;" :: "n"(n) : "memory")

__device__ __forceinline__ uint32_t f2tf(float f) {
    uint32_t r;
    asm("cvt.rna.tf32.f32 %0, %1;" : "=r"(r) : "f"(f));
    return r;
}
__device__ __forceinline__ void mma8(float* c, const uint32_t* a, const uint32_t* b) {
    asm volatile(
        "mma.sync.aligned.m16n8k8.row.col.f32.tf32.tf32.f32 "
        "{%0,%1,%2,%3}, {%4,%5,%6,%7}, {%8,%9}, {%0,%1,%2,%3};"
        : "+f"(c[0]), "+f"(c[1]), "+f"(c[2]), "+f"(c[3])
        : "r"(a[0]), "r"(a[1]), "r"(a[2]), "r"(a[3]), "r"(b[0]), "r"(b[1]));
}
__device__ __forceinline__ float silu(float g) { return g / (1.f + __expf(-g)); }

// Row stride 24 u32 (96B): row bases mod 32 = {0,24,16,8} -> disjoint octants.
// k-permutation: logical mma lane lm <-> phys col 2lm, lm+4 <-> 2lm+1, so each
// fragment pair is ONE LDS.64 from the natural-order tile.
#define AROW 24

// ---------------- init / x pre-round ----------------
__global__ void init_kernel() {
    if (threadIdx.x < NE) d_cnt[threadIdx.x] = 0;
}
__global__ void xround_kernel(const float4* __restrict__ x, float4* __restrict__ xr) {
    const int i = blockIdx.x * 256 + threadIdx.x;
    float4 v = x[i];
    v.x = __uint_as_float(f2tf(v.x));
    v.y = __uint_as_float(f2tf(v.y));
    v.z = __uint_as_float(f2tf(v.z));
    v.w = __uint_as_float(f2tf(v.w));
    xr[i] = v;
}

// ---------------- gate (reads raw x) ----------------
__global__ void gate_kernel(const float* __restrict__ x,
                            const float* __restrict__ gw,
                            const float* __restrict__ gb) {
    const int t = blockIdx.x;
    __shared__ float s_sc[NE];
    const int wid = threadIdx.x >> 5;
    const int lane = threadIdx.x & 31;
    const float* xr = x + (size_t)t * HD;
    const float* wr = gw + (size_t)wid * HD;
    float acc = 0.f;
    for (int k = lane; k < HD; k += 32) acc += xr[k] * wr[k];
    #pragma unroll
    for (int o = 16; o; o >>= 1) acc += __shfl_xor_sync(0xffffffffu, acc, o);
    if (lane == 0) s_sc[wid] = 1.f / (1.f + expf(-acc)) + gb[wid];
    __syncthreads();
    if (threadIdx.x != 0) return;

    float sc[NE];
    #pragma unroll
    for (int e = 0; e < NE; e++) sc[e] = s_sc[e];
    float gs[4];
    #pragma unroll
    for (int g = 0; g < 4; g++) {
        float m = sc[g * 4];
        #pragma unroll
        for (int j = 1; j < 4; j++) m = fmaxf(m, sc[g * 4 + j]);
        gs[g] = m;
    }
    int g0 = 0;
    for (int g = 1; g < 4; g++) if (gs[g] > gs[g0]) g0 = g;
    int g1 = -1;
    for (int g = 0; g < 4; g++) {
        if (g == g0) continue;
        if (g1 < 0 || gs[g] > gs[g1]) g1 = g;
    }
    float masked[NE];
    #pragma unroll
    for (int e = 0; e < NE; e++) {
        int g = e >> 2;
        masked[e] = (g == g0 || g == g1) ? sc[e] : 0.f;
    }
    int idx[TK]; float w[TK]; bool used[NE];
    #pragma unroll
    for (int e = 0; e < NE; e++) used[e] = false;
    float wsum = 0.f;
    for (int k = 0; k < TK; k++) {
        int best = -1;
        for (int e = 0; e < NE; e++) {
            if (used[e]) continue;
            if (best < 0 || masked[e] > masked[best]) best = e;
        }
        used[best] = true;
        idx[k] = best; w[k] = masked[best]; wsum += masked[best];
    }
    const float inv = 1.f / (wsum + 1e-6f);
    for (int k = 0; k < TK; k++) {
        int e = idx[k];
        int pos = atomicAdd(&d_cnt[e], 1);
        d_tok[e * NT + pos] = t;
        d_wt [e * NT + pos] = w[k] * inv * RSCALE;
    }
}

// ---------------- GEMM1: dual (gate,up) + SiLU, A pre-rounded --------------
// Tile 128M x 64N dual, Kc=16, 3-stage cp.async.
// Stage u32 layout: A[128*24] @0 | G[64*24] @3072 | U[64*24] @4608
#define G1_STAGE 24576
#define G1_SMEM  (512 + 3 * G1_STAGE)
template <bool GATHER>
__global__ void __launch_bounds__(256, 2)
gemm1_mma(const float* __restrict__ X,
          const float* __restrict__ Wg_, const float* __restrict__ Wu_,
          float* __restrict__ H_, int ldH, int K) {
    const int e = blockIdx.z;
    int M; const int* toks = nullptr; const float *Wg, *Wu; float* Ho;
    if (GATHER) {
        M = d_cnt[e]; toks = d_tok + e * NT;
        Wg = Wg_ + (size_t)e * ID * HD;
        Wu = Wu_ + (size_t)e * ID * HD;
        Ho = H_ + (size_t)e * NT * ID;
    } else {
        M = NT; Wg = Wg_; Wu = Wu_; Ho = H_;
    }
    const int m0 = blockIdx.y * 128;
    if (m0 >= M) return;
    const int n0 = blockIdx.x * 64;

    extern __shared__ char smem[];
    int* s_tok = (int*)smem;
    const int tid = threadIdx.x, lane = tid & 31, wid = tid >> 5;
    const int wr = wid >> 2, wc = wid & 3;
    if (GATHER && tid < 128) s_tok[tid] = (m0 + tid < M) ? toks[m0 + tid] : 0;
    __syncthreads();

    // loader (same as R3): row = tid/4 (0..63), ch = tid%4
    const int lrow = tid >> 2, lch = tid & 3;
    const bool ok0 = (m0 + lrow) < M;
    const bool ok1 = (m0 + lrow + 64) < M;
    int ar0 = 0, ar1 = 0;
    if (GATHER) { ar0 = ok0 ? s_tok[lrow] : 0; ar1 = ok1 ? s_tok[lrow + 64] : 0; }
    else        { ar0 = ok0 ? m0 + lrow : 0;   ar1 = ok1 ? m0 + lrow + 64 : 0; }
    const float* A0 = X + (size_t)ar0 * HD + lch * 4;
    const float* A1 = X + (size_t)ar1 * HD + lch * 4;
    const float* G0 = Wg + (size_t)(n0 + lrow) * HD + lch * 4;
    const float* U0 = Wu + (size_t)(n0 + lrow) * HD + lch * 4;
    const uint32_t sb = smem_u32(smem) + 512;
    const uint32_t w0 = (uint32_t)((lrow * AROW + lch * 4) * 4);
    const uint32_t sz0 = ok0 ? 16u : 0u, sz1 = ok1 ? 16u : 0u;

    const int C = K >> 4;
    auto load = [&](int c, int buf) {
        const int off = c * 16;
        const uint32_t d = sb + buf * G1_STAGE + w0;
        CP_ASYNC(d,                 A0 + off, sz0);
        CP_ASYNC(d + 64 * AROW * 4, A1 + off, sz1);
        CP_ASYNC(d + 12288,         G0 + off, 16);
        CP_ASYNC(d + 18432,         U0 + off, 16);
    };

    float cg[4][2][4] = {}, cu[4][2][4] = {};
    #pragma unroll
    for (int s = 0; s < 2; s++) { if (s < C) load(s, s); CP_COMMIT(); }

    const uint32_t* SBASE = (const uint32_t*)(smem + 512);
    const int l4 = lane >> 2, lm = lane & 3;
    const int a_off = (wr * 64 + l4) * AROW + 2 * lm;
    const int g_off = 3072 + (wc * 16 + l4) * AROW + 2 * lm;
    #pragma unroll 1
    for (int c = 0; c < C; c++) {
        CP_WAIT(1);
        __syncthreads();
        const int nc = c + 2;
        if (nc < C) load(nc, nc % 3);
        CP_COMMIT();
        const uint32_t* S = SBASE + (c % 3) * (G1_STAGE / 4);
        #pragma unroll
        for (int ks = 0; ks < 2; ks++) {
            uint32_t a[4][4];
            #pragma unroll
            for (int mi = 0; mi < 4; mi++) {
                const uint32_t* pa = S + a_off + mi * (16 * AROW) + ks * 8;
                uint2 p = *(const uint2*)pa;                 // rows l4:   (2lm, 2lm+1)
                uint2 q = *(const uint2*)(pa + 8 * AROW);    // rows l4+8
                a[mi][0] = p.x; a[mi][1] = q.x; a[mi][2] = p.y; a[mi][3] = q.y;
            }
            #pragma unroll
            for (int ni = 0; ni < 2; ni++) {
                const uint32_t* pg = S + g_off + ni * (8 * AROW) + ks * 8;
                uint2 vg = *(const uint2*)pg;
                uint2 vu = *(const uint2*)(pg + 64 * AROW);  // U block
                uint32_t bg[2] = { f2tf(__uint_as_float(vg.x)), f2tf(__uint_as_float(vg.y)) };
                uint32_t bu[2] = { f2tf(__uint_as_float(vu.x)), f2tf(__uint_as_float(vu.y)) };
                #pragma unroll
                for (int mi = 0; mi < 4; mi++) {
                    mma8(cg[mi][ni], a[mi], bg);
                    mma8(cu[mi][ni], a[mi], bu);
                }
            }
        }
    }
    // epilogue: silu(g)*u, rounded to tf32 so gemm2's A needs no CVT
    #pragma unroll
    for (int mi = 0; mi < 4; mi++)
        #pragma unroll
        for (int ni = 0; ni < 2; ni++) {
            const int r = m0 + wr * 64 + mi * 16 + l4;
            const int cc = n0 + wc * 16 + ni * 8 + 2 * lm;
            if (r < M) {
                float2 v = { __uint_as_float(f2tf(silu(cg[mi][ni][0]) * cu[mi][ni][0])),
                             __uint_as_float(f2tf(silu(cg[mi][ni][1]) * cu[mi][ni][1])) };
                *(float2*)(Ho + (size_t)r * ldH + cc) = v;
            }
            if (r + 8 < M) {
                float2 v = { __uint_as_float(f2tf(silu(cg[mi][ni][2]) * cu[mi][ni][2])),
                             __uint_as_float(f2tf(silu(cg[mi][ni][3]) * cu[mi][ni][3])) };
                *(float2*)(Ho + (size_t)(r + 8) * ldH + cc) = v;
            }
        }
}

// ---------------- GEMM2: down, A pre-rounded -------------------------------
// Tile 128M x 128N, Kc=16, 4-stage. Stage: A[128*24] @0 | B[128*24] @3072
#define G2_STAGE 24576
#define G2_SMEM  (1024 + 4 * G2_STAGE)
template <bool ROUTED>
__global__ void __launch_bounds__(256, 2)
gemm2_mma(const float* __restrict__ Hin_, const float* __restrict__ Wd_,
          float* __restrict__ Out, int K) {
    const int e = blockIdx.z;
    int M; const float *Hin, *Wd; const int* toks = nullptr; const float* wts = nullptr;
    if (ROUTED) {
        M = d_cnt[e];
        Hin = Hin_ + (size_t)e * NT * ID;
        Wd  = Wd_  + (size_t)e * HD * ID;
        toks = d_tok + e * NT; wts = d_wt + e * NT;
    } else {
        M = NT; Hin = Hin_; Wd = Wd_;
    }
    const int m0 = blockIdx.y * 128;
    if (m0 >= M) return;
    const int n0 = blockIdx.x * 128;

    extern __shared__ char smem[];
    int*   s_tok = (int*)smem;
    float* s_wt  = (float*)(smem + 512);
    const int tid = threadIdx.x, lane = tid & 31, wid = tid >> 5;
    const int wr = wid >> 2, wc = wid & 3;
    if (ROUTED && tid < 128) {
        const bool ok = m0 + tid < M;
        s_tok[tid] = ok ? toks[m0 + tid] : 0;
        s_wt [tid] = ok ? wts [m0 + tid] : 0.f;
    }
    __syncthreads();

    const int lrow = tid >> 2, lch = tid & 3;
    const bool ok0 = (m0 + lrow) < M;
    const bool ok1 = (m0 + lrow + 64) < M;
    const float* A0 = Hin + (size_t)(ok0 ? m0 + lrow : 0) * K + lch * 4;
    const float* A1 = Hin + (size_t)(ok1 ? m0 + lrow + 64 : 0) * K + lch * 4;
    const float* B0 = Wd + (size_t)(n0 + lrow) * K + lch * 4;
    const float* B1 = Wd + (size_t)(n0 + lrow + 64) * K + lch * 4;
    const uint32_t sb = smem_u32(smem) + 1024;
    const uint32_t w0 = (uint32_t)((lrow * AROW + lch * 4) * 4);
    const uint32_t sz0 = ok0 ? 16u : 0u, sz1 = ok1 ? 16u : 0u;

    const int C = K >> 4;
    auto load = [&](int c, int buf) {
        const int off = c * 16;
        const uint32_t d = sb + buf * G2_STAGE + w0;
        CP_ASYNC(d,                         A0 + off, sz0);
        CP_ASYNC(d + 64 * AROW * 4,         A1 + off, sz1);
        CP_ASYNC(d + 12288,                 B0 + off, 16);
        CP_ASYNC(d + 12288 + 64 * AROW * 4, B1 + off, 16);
    };

    float acc[4][4][4] = {};
    #pragma unroll
    for (int s = 0; s < 3; s++) { if (s < C) load(s, s); CP_COMMIT(); }

    const uint32_t* SBASE = (const uint32_t*)(smem + 1024);
    const int l4 = lane >> 2, lm = lane & 3;
    const int a_off = (wr * 64 + l4) * AROW + 2 * lm;
    const int b_off = 3072 + (wc * 32 + l4) * AROW + 2 * lm;
    #pragma unroll 1
    for (int c = 0; c < C; c++) {
        CP_WAIT(2);
        __syncthreads();
        const int nc = c + 3;
        if (nc < C) load(nc, nc & 3);
        CP_COMMIT();
        const uint32_t* S = SBASE + (c & 3) * (G2_STAGE / 4);
        #pragma unroll
        for (int ks = 0; ks < 2; ks++) {
            uint32_t a[4][4];
            #pragma unroll
            for (int mi = 0; mi < 4; mi++) {
                const uint32_t* pa = S + a_off + mi * (16 * AROW) + ks * 8;
                uint2 p = *(const uint2*)pa;
                uint2 q = *(const uint2*)(pa + 8 * AROW);
                a[mi][0] = p.x; a[mi][1] = q.x; a[mi][2] = p.y; a[mi][3] = q.y;
            }
            #pragma unroll
            for (int ni = 0; ni < 4; ni++) {
                uint2 vb = *(const uint2*)(S + b_off + ni * (8 * AROW) + ks * 8);
                uint32_t b[2] = { f2tf(__uint_as_float(vb.x)), f2tf(__uint_as_float(vb.y)) };
                #pragma unroll
                for (int mi = 0; mi < 4; mi++)
                    mma8(acc[mi][ni], a[mi], b);
            }
        }
    }
    #pragma unroll
    for (int mi = 0; mi < 4; mi++) {
        const int rl0 = wr * 64 + mi * 16 + l4;
        #pragma unroll
        for (int ni = 0; ni < 4; ni++) {
            const int cc = n0 + wc * 32 + ni * 8 + 2 * lm;
            #pragma unroll
            for (int h = 0; h < 2; h++) {
                const int rl = rl0 + h * 8;
                if (m0 + rl >= M) continue;
                const float v0 = acc[mi][ni][2 * h + 0];
                const float v1 = acc[mi][ni][2 * h + 1];
                if (ROUTED) {
                    const float w = s_wt[rl];
                    float* o = Out + (size_t)s_tok[rl] * HD + cc;
                    atomicAdd(o + 0, w * v0);
                    atomicAdd(o + 1, w * v1);
                } else {
                    float2 v = { v0, v1 };
                    *(float2*)(Out + (size_t)(m0 + rl) * HD + cc) = v;
                }
            }
        }
    }
}

// ---------------- launch ----------------
extern "C" void kernel_launch(void* const* d_in, const int* in_sizes, int n_in,
                              void* d_out, int out_size) {
    const float* x       = (const float*)d_in[0];
    const float* gate_w  = (const float*)d_in[1];
    const float* gate_b  = (const float*)d_in[2];
    const float* w_gate  = (const float*)d_in[3];
    const float* w_up    = (const float*)d_in[4];
    const float* w_down  = (const float*)d_in[5];
    const float* sw_gate = (const float*)d_in[6];
    const float* sw_up   = (const float*)d_in[7];
    const float* sw_down = (const float*)d_in[8];
    float* out = (float*)d_out;

    float* hbuf; cudaGetSymbolAddress((void**)&hbuf, d_hbuf);
    float* hsh;  cudaGetSymbolAddress((void**)&hsh,  d_hsh);
    float* xr;   cudaGetSymbolAddress((void**)&xr,   d_xr);

    cudaFuncSetAttribute(gemm1_mma<true>,  cudaFuncAttributeMaxDynamicSharedMemorySize, G1_SMEM);
    cudaFuncSetAttribute(gemm1_mma<false>, cudaFuncAttributeMaxDynamicSharedMemorySize, G1_SMEM);
    cudaFuncSetAttribute(gemm2_mma<true>,  cudaFuncAttributeMaxDynamicSharedMemorySize, G2_SMEM);
    cudaFuncSetAttribute(gemm2_mma<false>, cudaFuncAttributeMaxDynamicSharedMemorySize, G2_SMEM);

    init_kernel<<<1, 32>>>();
    xround_kernel<<<(NT * HD) / 1024, 256>>>((const float4*)x, (float4*)xr);
    gate_kernel<<<NT, 512>>>(x, gate_w, gate_b);

    // routed gate/up + silu (A = rounded x, gathered)
    gemm1_mma<true><<<dim3(ID / 64, NT / 128, NE), 256, G1_SMEM>>>(
        xr, w_gate, w_up, hbuf, ID, HD);
    // shared gate/up + silu
    gemm1_mma<false><<<dim3(SID / 64, NT / 128, 1), 256, G1_SMEM>>>(
        xr, sw_gate, sw_up, hsh, SID, HD);
    // shared down: plain writes initialize d_out fully
    gemm2_mma<false><<<dim3(HD / 128, NT / 128, 1), 256, G2_SMEM>>>(
        hsh, sw_down, out, SID);
    // routed down: atomic scatter-add on top of shared result
    gemm2_mma<true><<<dim3(HD / 128, NT / 128, NE), 256, G2_SMEM>>>(
        hbuf, w_down, out, ID);
}

// round 8
// speedup vs baseline: 2.0946x; 1.2668x over previous
#include <cuda_runtime.h>
#include <cuda_fp16.h>
#include <math.h>
#include <cstdint>

#define HD 2048
#define ID 1408
#define NE 16
#define TK 4
#define NT 1024
#define SID 2816
#define RSCALE 2.5f

// ---------------- scratch ----------------
__device__ int    d_cnt[NE];
__device__ int    d_tok[NE * NT];
__device__ float  d_wt [NE * NT];
// fp16 pair-permuted copies (K-groups of 16 stored as [p0,p4,p1,p5,p2,p6,p3,p7])
__device__ __half w_g16[NE * ID * HD];
__device__ __half w_u16[NE * ID * HD];
__device__ __half w_d16[NE * HD * ID];
__device__ __half sw_g16[SID * HD];
__device__ __half sw_u16[SID * HD];
__device__ __half sw_d16[HD * SID];
__device__ __half x16  [NT * HD];
__device__ __half h_r16[NE * NT * ID];
__device__ __half h_s16[NT * SID];

// ---------------- PTX helpers ----------------
__device__ __forceinline__ uint32_t smem_u32(const void* p) {
    uint32_t a;
    asm("{ .reg .u64 t; cvta.to.shared.u64 t, %1; cvt.u32.u64 %0, t; }"
        : "=r"(a) : "l"(p));
    return a;
}
#define CP_ASYNC(dst, src, sz) \
    asm volatile("cp.async.cg.shared.global [%0], [%1], 16, %2;" \
                 :: "r"(dst), "l"(src), "r"(sz) : "memory")
#define CP_COMMIT() asm volatile("cp.async.commit_group;" ::: "memory")
#define CP_WAIT(n)  asm volatile("cp.async.wait_group %0;" :: "n"(n) : "memory")

// fp16 mma m16n8k16, fp32 accumulate
__device__ __forceinline__ void mma16(float* c, const uint32_t* a, const uint32_t* b) {
    asm volatile(
        "mma.sync.aligned.m16n8k16.row.col.f32.f16.f16.f32 "
        "{%0,%1,%2,%3}, {%4,%5,%6,%7}, {%8,%9}, {%0,%1,%2,%3};"
        : "+f"(c[0]), "+f"(c[1]), "+f"(c[2]), "+f"(c[3])
        : "r"(a[0]), "r"(a[1]), "r"(a[2]), "r"(a[3]), "r"(b[0]), "r"(b[1]));
}
__device__ __forceinline__ float silu(float g) { return g / (1.f + __expf(-g)); }
__device__ __forceinline__ uint32_t h2u(__half2 h) {
    uint32_t u; *(__half2*)&u = h; return u;
}

// smem rows: 64B data (32 fp16, permuted) + 32B pad = 96B (12 uint2)
#define ROWB 96
#define ROWU2 12

// ---------------- init / converts ----------------
__global__ void init_kernel() {
    if (threadIdx.x < NE) d_cnt[threadIdx.x] = 0;
}
// fp32 -> fp16, permuting each flat 16-element group to pair order
// [p0,p4,p1,p5,p2,p6,p3,p7] (p_j = elems 2j,2j+1)
__global__ void conv_perm(const float4* __restrict__ src, uint4* __restrict__ dst) {
    const size_t t = (size_t)blockIdx.x * 256 + threadIdx.x;
    float4 f0 = src[4 * t], f1 = src[4 * t + 1], f2 = src[4 * t + 2], f3 = src[4 * t + 3];
    const float f[16] = { f0.x, f0.y, f0.z, f0.w, f1.x, f1.y, f1.z, f1.w,
                          f2.x, f2.y, f2.z, f2.w, f3.x, f3.y, f3.z, f3.w };
    uint32_t h[8];
    #pragma unroll
    for (int s = 0; s < 8; s++) {
        const int j = (s & 1) ? ((s >> 1) + 4) : (s >> 1);
        h[s] = h2u(__floats2half2_rn(f[2 * j], f[2 * j + 1]));
    }
    dst[2 * t]     = make_uint4(h[0], h[1], h[2], h[3]);
    dst[2 * t + 1] = make_uint4(h[4], h[5], h[6], h[7]);
}

// ---------------- gate (raw fp32 x) ----------------
__global__ void gate_kernel(const float* __restrict__ x,
                            const float* __restrict__ gw,
                            const float* __restrict__ gb) {
    const int t = blockIdx.x;
    __shared__ float s_sc[NE];
    const int wid = threadIdx.x >> 5;
    const int lane = threadIdx.x & 31;
    const float* xr = x + (size_t)t * HD;
    const float* wr = gw + (size_t)wid * HD;
    float acc = 0.f;
    for (int k = lane; k < HD; k += 32) acc += xr[k] * wr[k];
    #pragma unroll
    for (int o = 16; o; o >>= 1) acc += __shfl_xor_sync(0xffffffffu, acc, o);
    if (lane == 0) s_sc[wid] = 1.f / (1.f + expf(-acc)) + gb[wid];
    __syncthreads();
    if (threadIdx.x != 0) return;

    float sc[NE];
    #pragma unroll
    for (int e = 0; e < NE; e++) sc[e] = s_sc[e];
    float gs[4];
    #pragma unroll
    for (int g = 0; g < 4; g++) {
        float m = sc[g * 4];
        #pragma unroll
        for (int j = 1; j < 4; j++) m = fmaxf(m, sc[g * 4 + j]);
        gs[g] = m;
    }
    int g0 = 0;
    for (int g = 1; g < 4; g++) if (gs[g] > gs[g0]) g0 = g;
    int g1 = -1;
    for (int g = 0; g < 4; g++) {
        if (g == g0) continue;
        if (g1 < 0 || gs[g] > gs[g1]) g1 = g;
    }
    float masked[NE];
    #pragma unroll
    for (int e = 0; e < NE; e++) {
        int g = e >> 2;
        masked[e] = (g == g0 || g == g1) ? sc[e] : 0.f;
    }
    int idx[TK]; float w[TK]; bool used[NE];
    #pragma unroll
    for (int e = 0; e < NE; e++) used[e] = false;
    float wsum = 0.f;
    for (int k = 0; k < TK; k++) {
        int best = -1;
        for (int e = 0; e < NE; e++) {
            if (used[e]) continue;
            if (best < 0 || masked[e] > masked[best]) best = e;
        }
        used[best] = true;
        idx[k] = best; w[k] = masked[best]; wsum += masked[best];
    }
    const float inv = 1.f / (wsum + 1e-6f);
    for (int k = 0; k < TK; k++) {
        int e = idx[k];
        int pos = atomicAdd(&d_cnt[e], 1);
        d_tok[e * NT + pos] = t;
        d_wt [e * NT + pos] = w[k] * inv * RSCALE;
    }
}

// ---------------- GEMM1 fp16: dual (gate,up) + SiLU ------------------------
// Tile 128M x 64N dual, Kc=32, 3-stage cp.async.
// Stage: A 128x96B @0 | G 64x96B @12288 | U @18432 ; stride 24576
#define G1_STAGE 24576
#define G1_SMEM  (512 + 3 * G1_STAGE)
template <bool GATHER>
__global__ void __launch_bounds__(256, 2)
gemm1_h(const __half* __restrict__ X,
        const __half* __restrict__ Wg_, const __half* __restrict__ Wu_,
        __half* __restrict__ H_, int ldH, int K) {
    const int e = blockIdx.z;
    int M; const int* toks = nullptr; const __half *Wg, *Wu; __half* Ho;
    if (GATHER) {
        M = d_cnt[e]; toks = d_tok + e * NT;
        Wg = Wg_ + (size_t)e * ID * HD;
        Wu = Wu_ + (size_t)e * ID * HD;
        Ho = H_ + (size_t)e * NT * ID;
    } else {
        M = NT; Wg = Wg_; Wu = Wu_; Ho = H_;
    }
    const int m0 = blockIdx.y * 128;
    if (m0 >= M) return;
    const int n0 = blockIdx.x * 64;

    extern __shared__ char smem[];
    int* s_tok = (int*)smem;
    const int tid = threadIdx.x, lane = tid & 31, wid = tid >> 5;
    const int wr = wid >> 2, wc = wid & 3;
    if (GATHER && tid < 128) s_tok[tid] = (m0 + tid < M) ? toks[m0 + tid] : 0;
    __syncthreads();

    // loader: A row tid>>1 (2 segs), G row tid>>2 (1 seg), U row tid>>2 (1 seg)
    const int rA = tid >> 1, sA = (tid & 1) * 2;
    const int rW = tid >> 2, sW = tid & 3;
    const bool aok = (m0 + rA) < M;
    const int ar = GATHER ? (aok ? s_tok[rA] : 0) : (aok ? m0 + rA : 0);
    const char* Ap = (const char*)(X + (size_t)ar * K);
    const char* Gp = (const char*)(Wg + (size_t)(n0 + rW) * K);
    const char* Up = (const char*)(Wu + (size_t)(n0 + rW) * K);
    const uint32_t sb = smem_u32(smem) + 512;
    const uint32_t dA = sb + rA * ROWB + sA * 16;
    const uint32_t dG = sb + 12288 + rW * ROWB + sW * 16;
    const uint32_t dU = sb + 18432 + rW * ROWB + sW * 16;
    const uint32_t szA = aok ? 16u : 0u;

    const int C = K >> 5;   // 32 cols per chunk
    auto load = [&](int c, int buf) {
        const int off = c * 64;
        const uint32_t b = buf * G1_STAGE;
        CP_ASYNC(dA + b,      Ap + off + sA * 16,      szA);
        CP_ASYNC(dA + b + 16, Ap + off + sA * 16 + 16, szA);
        CP_ASYNC(dG + b,      Gp + off + sW * 16, 16);
        CP_ASYNC(dU + b,      Up + off + sW * 16, 16);
    };

    float cg[4][2][4] = {}, cu[4][2][4] = {};
    #pragma unroll
    for (int s = 0; s < 2; s++) { if (s < C) load(s, s); CP_COMMIT(); }

    const int l4 = lane >> 2, lm = lane & 3;
    const int a_off = (wr * 64 + l4) * ROWU2 + lm;
    const int g_off = 1536 + (wc * 16 + l4) * ROWU2 + lm;   // 12288B/8
    #pragma unroll 1
    for (int c = 0; c < C; c++) {
        CP_WAIT(1);
        __syncthreads();
        const int nc = c + 2;
        if (nc < C) load(nc, nc % 3);
        CP_COMMIT();
        const uint2* S = (const uint2*)(smem + 512 + (c % 3) * G1_STAGE);
        #pragma unroll
        for (int ks = 0; ks < 2; ks++) {
            uint32_t a[4][4];
            #pragma unroll
            for (int mi = 0; mi < 4; mi++) {
                const uint2 p = S[a_off + mi * (16 * ROWU2) + ks * 4];
                const uint2 q = S[a_off + mi * (16 * ROWU2) + 8 * ROWU2 + ks * 4];
                a[mi][0] = p.x; a[mi][1] = q.x; a[mi][2] = p.y; a[mi][3] = q.y;
            }
            #pragma unroll
            for (int ni = 0; ni < 2; ni++) {
                const uint2 vg = S[g_off + ni * (8 * ROWU2) + ks * 4];
                const uint2 vu = S[g_off + 768 + ni * (8 * ROWU2) + ks * 4];
                uint32_t bg[2] = { vg.x, vg.y };
                uint32_t bu[2] = { vu.x, vu.y };
                #pragma unroll
                for (int mi = 0; mi < 4; mi++) {
                    mma16(cg[mi][ni], a[mi], bg);
                    mma16(cu[mi][ni], a[mi], bu);
                }
            }
        }
    }
    // epilogue: silu(g)*u -> fp16 pair-permuted (slot 2lm = ni0 pair, 2lm+1 = ni1 pair)
    #pragma unroll
    for (int mi = 0; mi < 4; mi++)
        #pragma unroll
        for (int h = 0; h < 2; h++) {
            const int r = m0 + wr * 64 + mi * 16 + l4 + h * 8;
            if (r >= M) continue;
            const float v0 = silu(cg[mi][0][2 * h + 0]) * cu[mi][0][2 * h + 0];
            const float v1 = silu(cg[mi][0][2 * h + 1]) * cu[mi][0][2 * h + 1];
            const float v2 = silu(cg[mi][1][2 * h + 0]) * cu[mi][1][2 * h + 0];
            const float v3 = silu(cg[mi][1][2 * h + 1]) * cu[mi][1][2 * h + 1];
            uint2 val = { h2u(__floats2half2_rn(v0, v1)), h2u(__floats2half2_rn(v2, v3)) };
            ((uint2*)(Ho + (size_t)r * ldH + n0 + wc * 16))[lm] = val;
        }
}

// ---------------- GEMM2 fp16: down --------------------------------------
// Tile 128M x 128N, Kc=32, 4-stage. Stage: A 128x96B @0 | B @12288 ; 24576
#define G2_STAGE 24576
#define G2_SMEM  (1024 + 4 * G2_STAGE)
template <bool ROUTED>
__global__ void __launch_bounds__(256, 2)
gemm2_h(const __half* __restrict__ Hin_, const __half* __restrict__ Wd_,
        float* __restrict__ Out, int K) {
    const int e = blockIdx.z;
    int M; const __half *Hin, *Wd; const int* toks = nullptr; const float* wts = nullptr;
    if (ROUTED) {
        M = d_cnt[e];
        Hin = Hin_ + (size_t)e * NT * ID;
        Wd  = Wd_  + (size_t)e * HD * ID;
        toks = d_tok + e * NT; wts = d_wt + e * NT;
    } else {
        M = NT; Hin = Hin_; Wd = Wd_;
    }
    const int m0 = blockIdx.y * 128;
    if (m0 >= M) return;
    const int n0 = blockIdx.x * 128;

    extern __shared__ char smem[];
    int*   s_tok = (int*)smem;
    float* s_wt  = (float*)(smem + 512);
    const int tid = threadIdx.x, lane = tid & 31, wid = tid >> 5;
    const int wr = wid >> 2, wc = wid & 3;
    if (ROUTED && tid < 128) {
        const bool ok = m0 + tid < M;
        s_tok[tid] = ok ? toks[m0 + tid] : 0;
        s_wt [tid] = ok ? wts [m0 + tid] : 0.f;
    }
    __syncthreads();

    const int rA = tid >> 1, sA = (tid & 1) * 2;
    const bool aok = (m0 + rA) < M;
    const char* Ap = (const char*)(Hin + (size_t)(aok ? m0 + rA : 0) * K);
    const char* Bp = (const char*)(Wd + (size_t)(n0 + rA) * K);
    const uint32_t sb = smem_u32(smem) + 1024;
    const uint32_t dA = sb + rA * ROWB + sA * 16;
    const uint32_t dB = sb + 12288 + rA * ROWB + sA * 16;
    const uint32_t szA = aok ? 16u : 0u;

    const int C = K >> 5;
    auto load = [&](int c, int buf) {
        const int off = c * 64;
        const uint32_t b = buf * G2_STAGE;
        CP_ASYNC(dA + b,      Ap + off + sA * 16,      szA);
        CP_ASYNC(dA + b + 16, Ap + off + sA * 16 + 16, szA);
        CP_ASYNC(dB + b,      Bp + off + sA * 16,      16);
        CP_ASYNC(dB + b + 16, Bp + off + sA * 16 + 16, 16);
    };

    float acc[4][4][4] = {};
    #pragma unroll
    for (int s = 0; s < 3; s++) { if (s < C) load(s, s); CP_COMMIT(); }

    const int l4 = lane >> 2, lm = lane & 3;
    const int a_off = (wr * 64 + l4) * ROWU2 + lm;
    const int b_off = 1536 + (wc * 32 + l4) * ROWU2 + lm;
    #pragma unroll 1
    for (int c = 0; c < C; c++) {
        CP_WAIT(2);
        __syncthreads();
        const int nc = c + 3;
        if (nc < C) load(nc, nc & 3);
        CP_COMMIT();
        const uint2* S = (const uint2*)(smem + 1024 + (c & 3) * G2_STAGE);
        #pragma unroll
        for (int ks = 0; ks < 2; ks++) {
            uint32_t a[4][4];
            #pragma unroll
            for (int mi = 0; mi < 4; mi++) {
                const uint2 p = S[a_off + mi * (16 * ROWU2) + ks * 4];
                const uint2 q = S[a_off + mi * (16 * ROWU2) + 8 * ROWU2 + ks * 4];
                a[mi][0] = p.x; a[mi][1] = q.x; a[mi][2] = p.y; a[mi][3] = q.y;
            }
            #pragma unroll
            for (int ni = 0; ni < 4; ni++) {
                const uint2 vb = S[b_off + ni * (8 * ROWU2) + ks * 4];
                uint32_t b[2] = { vb.x, vb.y };
                #pragma unroll
                for (int mi = 0; mi < 4; mi++)
                    mma16(acc[mi][ni], a[mi], b);
            }
        }
    }
    #pragma unroll
    for (int mi = 0; mi < 4; mi++) {
        const int rl0 = wr * 64 + mi * 16 + l4;
        #pragma unroll
        for (int ni = 0; ni < 4; ni++) {
            const int cc = n0 + wc * 32 + ni * 8 + 2 * lm;
            #pragma unroll
            for (int h = 0; h < 2; h++) {
                const int rl = rl0 + h * 8;
                if (m0 + rl >= M) continue;
                const float v0 = acc[mi][ni][2 * h + 0];
                const float v1 = acc[mi][ni][2 * h + 1];
                if (ROUTED) {
                    const float w = s_wt[rl];
                    float* o = Out + (size_t)s_tok[rl] * HD + cc;
                    atomicAdd(o + 0, w * v0);
                    atomicAdd(o + 1, w * v1);
                } else {
                    float2 v = { v0, v1 };
                    *(float2*)(Out + (size_t)(m0 + rl) * HD + cc) = v;
                }
            }
        }
    }
}

// ---------------- launch ----------------
extern "C" void kernel_launch(void* const* d_in, const int* in_sizes, int n_in,
                              void* d_out, int out_size) {
    const float* x       = (const float*)d_in[0];
    const float* gate_w  = (const float*)d_in[1];
    const float* gate_b  = (const float*)d_in[2];
    const float* w_gate  = (const float*)d_in[3];
    const float* w_up    = (const float*)d_in[4];
    const float* w_down  = (const float*)d_in[5];
    const float* sw_gate = (const float*)d_in[6];
    const float* sw_up   = (const float*)d_in[7];
    const float* sw_down = (const float*)d_in[8];
    float* out = (float*)d_out;

    __half *wg16, *wu16, *wd16, *sg16, *su16, *sd16, *xh, *hr, *hs;
    cudaGetSymbolAddress((void**)&wg16, w_g16);
    cudaGetSymbolAddress((void**)&wu16, w_u16);
    cudaGetSymbolAddress((void**)&wd16, w_d16);
    cudaGetSymbolAddress((void**)&sg16, sw_g16);
    cudaGetSymbolAddress((void**)&su16, sw_u16);
    cudaGetSymbolAddress((void**)&sd16, sw_d16);
    cudaGetSymbolAddress((void**)&xh,   x16);
    cudaGetSymbolAddress((void**)&hr,   h_r16);
    cudaGetSymbolAddress((void**)&hs,   h_s16);

    cudaFuncSetAttribute(gemm1_h<true>,  cudaFuncAttributeMaxDynamicSharedMemorySize, G1_SMEM);
    cudaFuncSetAttribute(gemm1_h<false>, cudaFuncAttributeMaxDynamicSharedMemorySize, G1_SMEM);
    cudaFuncSetAttribute(gemm2_h<true>,  cudaFuncAttributeMaxDynamicSharedMemorySize, G2_SMEM);
    cudaFuncSetAttribute(gemm2_h<false>, cudaFuncAttributeMaxDynamicSharedMemorySize, G2_SMEM);

    init_kernel<<<1, 32>>>();
    // convert + permute: routed weights (11264 blocks each), shared (1408), x (512)
    conv_perm<<<11264, 256>>>((const float4*)w_gate,  (uint4*)wg16);
    conv_perm<<<11264, 256>>>((const float4*)w_up,    (uint4*)wu16);
    conv_perm<<<11264, 256>>>((const float4*)w_down,  (uint4*)wd16);
    conv_perm<<<1408,  256>>>((const float4*)sw_gate, (uint4*)sg16);
    conv_perm<<<1408,  256>>>((const float4*)sw_up,   (uint4*)su16);
    conv_perm<<<1408,  256>>>((const float4*)sw_down, (uint4*)sd16);
    conv_perm<<<512,   256>>>((const float4*)x,       (uint4*)xh);
    gate_kernel<<<NT, 512>>>(x, gate_w, gate_b);

    // routed gate/up + silu
    gemm1_h<true><<<dim3(ID / 64, NT / 128, NE), 256, G1_SMEM>>>(
        xh, wg16, wu16, hr, ID, HD);
    // shared gate/up + silu
    gemm1_h<false><<<dim3(SID / 64, NT / 128, 1), 256, G1_SMEM>>>(
        xh, sg16, su16, hs, SID, HD);
    // shared down: plain stores initialize d_out fully
    gemm2_h<false><<<dim3(HD / 128, NT / 128, 1), 256, G2_SMEM>>>(
        hs, sd16, out, SID);
    // routed down: atomic scatter-add
    gemm2_h<true><<<dim3(HD / 128, NT / 128, NE), 256, G2_SMEM>>>(
        hr, wd16, out, ID);
}